// round 1
// baseline (speedup 1.0000x reference)
#include <cuda_runtime.h>
#include <cstdint>

// Problem constants (fixed by the dataset)
#define N0C 10000
#define N1C 40000
#define N2C 160000
#define E1C 240000
#define E2C 960000

// Static scratch (no allocation allowed)
__device__ float g_basis[E2C * 9];                 // 34.6 MB  (reused per level)
__device__ float g_Z[N2C * 9 * 16];                // 92.2 MB  (>= N1C*9*32 = 46.1 MB)
__device__ float g_bufA[N2C * 32];                 // 20.5 MB
__device__ float g_bufB[N2C * 32];                 // 20.5 MB

// ---------------------------------------------------------------------------
// Basis: open quadratic B-spline, kernel 3, degree 2, dim 2 -> 9 weights/edge
// ---------------------------------------------------------------------------
__global__ void basis_kernel(const float* __restrict__ pseudo,
                             float* __restrict__ basis, int E) {
    int e = blockIdx.x * blockDim.x + threadIdx.x;
    if (e >= E) return;
    float t0 = pseudo[2 * e + 0];
    float t1 = pseudo[2 * e + 1];
    float a0 = 0.5f * (1.f - t0) * (1.f - t0);
    float a1 = -t0 * t0 + t0 + 0.5f;
    float a2 = 0.5f * t0 * t0;
    float c0 = 0.5f * (1.f - t1) * (1.f - t1);
    float c1 = -t1 * t1 + t1 + 0.5f;
    float c2 = 0.5f * t1 * t1;
    float* b = basis + (size_t)e * 9;
    b[0] = a0 * c0; b[1] = a0 * c1; b[2] = a0 * c2;
    b[3] = a1 * c0; b[4] = a1 * c1; b[5] = a1 * c2;
    b[6] = a2 * c0; b[7] = a2 * c1; b[8] = a2 * c2;
}

// ---------------------------------------------------------------------------
// Node kernel: Z[n, 9*COUT] = X[n,:] @ Wcat ; O[n,:] = X[n,:] @ R + b
// X row n is assembled on the fly:
//   row r = gidx ? gidx[n] : n
//   c <  CA : xA[r*CA + c]   (optionally ReLU'd -- outputs of previous conv)
//   c >= CA : xB[r*(CIN-CA) + (c-CA)]   (skip connection, raw)
// Register tile: 128 threads = 32 lanes (out cols) x 4 groups; each thread
// computes 8 nodes x TN cols, TN = 10*COUT/32 (R folded in as a 10th "k").
// ---------------------------------------------------------------------------
template <int CIN, int COUT>
__global__ void node_kernel(const float* __restrict__ xA, int CA,
                            const float* __restrict__ xB,
                            const int* __restrict__ gidx, int reluA,
                            const float* __restrict__ W,
                            const float* __restrict__ Rm,
                            const float* __restrict__ bias,
                            float* __restrict__ Z, float* __restrict__ O,
                            int N) {
    constexpr int OUTW = 10 * COUT;         // 9*COUT spline cols + COUT root cols
    constexpr int TN = OUTW / 32;
    constexpr int CHUNK = (CIN < 16) ? CIN : 16;
    constexpr int NCHUNK = CIN / CHUNK;

    __shared__ float xs[CHUNK][32];
    __shared__ float ws[CHUNK][OUTW];
    __shared__ int rows[32];

    int tid = threadIdx.x;
    int lane = tid & 31;
    int ty = tid >> 5;
    int nodeBase = blockIdx.x * 32;

    if (tid < 32) {
        int n = nodeBase + tid;
        rows[tid] = gidx ? gidx[n] : n;
    }

    float acc[8][TN];
#pragma unroll
    for (int m = 0; m < 8; m++)
#pragma unroll
        for (int t = 0; t < TN; t++) acc[m][t] = 0.f;

    for (int c0 = 0; c0 < NCHUNK; c0++) {
        __syncthreads();
        // load x tile (32 nodes x CHUNK channels)
        for (int i = tid; i < 32 * CHUNK; i += 128) {
            int cc = i >> 5;
            int nn = i & 31;
            int c = c0 * CHUNK + cc;
            int r = rows[nn];
            float v;
            if (c < CA) {
                v = xA[(size_t)r * CA + c];
                if (reluA) v = fmaxf(v, 0.f);
            } else {
                v = xB[(size_t)r * (CIN - CA) + (c - CA)];
            }
            xs[cc][nn] = v;
        }
        // load weight tile (CHUNK x OUTW); cols [9*COUT, 10*COUT) come from R
        for (int i = tid; i < CHUNK * OUTW; i += 128) {
            int cc = i / OUTW;
            int j = i % OUTW;
            int c = c0 * CHUNK + cc;
            float w;
            if (j < 9 * COUT) {
                int k = j / COUT;
                int co = j % COUT;
                w = W[((size_t)k * CIN + c) * COUT + co];
            } else {
                int co = j - 9 * COUT;
                w = Rm[(size_t)c * COUT + co];
            }
            ws[cc][j] = w;
        }
        __syncthreads();
#pragma unroll
        for (int cc = 0; cc < CHUNK; cc++) {
            float xv[8];
#pragma unroll
            for (int m = 0; m < 8; m++) xv[m] = xs[cc][ty * 8 + m];
            float wv[TN];
#pragma unroll
            for (int t = 0; t < TN; t++) wv[t] = ws[cc][lane + 32 * t];
#pragma unroll
            for (int m = 0; m < 8; m++)
#pragma unroll
                for (int t = 0; t < TN; t++) acc[m][t] = fmaf(xv[m], wv[t], acc[m][t]);
        }
    }

#pragma unroll
    for (int m = 0; m < 8; m++) {
        int n = nodeBase + ty * 8 + m;
#pragma unroll
        for (int t = 0; t < TN; t++) {
            int j = lane + 32 * t;
            if (j < 9 * COUT) {
                Z[(size_t)n * (9 * COUT) + j] = acc[m][t];
            } else {
                int co = j - 9 * COUT;
                O[(size_t)n * COUT + co] = acc[m][t] + bias[co];
            }
        }
    }
}

// ---------------------------------------------------------------------------
// Edge kernel: m_e = sum_k basis[e,k] * Z[src_e, k, :], scatter-add to O[dst].
// COUT/4 threads per edge, each owning 4 consecutive channels (float4 loads).
// ---------------------------------------------------------------------------
template <int COUT>
__global__ void edge_kernel(const int* __restrict__ src,
                            const int* __restrict__ dst,
                            const float* __restrict__ basis,
                            const float* __restrict__ Z,
                            float* __restrict__ O, int E) {
    constexpr int TPE = COUT / 4;
    int tid = blockIdx.x * blockDim.x + threadIdx.x;
    int e = tid / TPE;
    int g = tid % TPE;
    if (e >= E) return;
    int s = src[e];
    int d = dst[e];
    const float4* zr = reinterpret_cast<const float4*>(Z + (size_t)s * (9 * COUT)) + g;
    const float* br = basis + (size_t)e * 9;
    float4 acc = make_float4(0.f, 0.f, 0.f, 0.f);
#pragma unroll
    for (int k = 0; k < 9; k++) {
        float bk = __ldg(br + k);
        float4 z = __ldg(zr + k * (COUT / 4));
        acc.x = fmaf(bk, z.x, acc.x);
        acc.y = fmaf(bk, z.y, acc.y);
        acc.z = fmaf(bk, z.z, acc.z);
        acc.w = fmaf(bk, z.w, acc.w);
    }
    float* o = O + (size_t)d * COUT + g * 4;
    atomicAdd(o + 0, acc.x);
    atomicAdd(o + 1, acc.y);
    atomicAdd(o + 2, acc.z);
    atomicAdd(o + 3, acc.w);
}

__global__ void relu_copy_kernel(const float* __restrict__ in,
                                 float* __restrict__ out, int n) {
    int i = blockIdx.x * blockDim.x + threadIdx.x;
    if (i < n) out[i] = fmaxf(in[i], 0.f);
}

// ---------------------------------------------------------------------------
extern "C" void kernel_launch(void* const* d_in, const int* in_sizes, int n_in,
                              void* d_out, int out_size) {
    const float* x0      = (const float*)d_in[0];
    const int*   unpool1 = (const int*)d_in[1];
    const int*   edge1   = (const int*)d_in[2];
    const float* pseudo1 = (const float*)d_in[3];
    const float* skip1   = (const float*)d_in[4];
    const int*   unpool2 = (const int*)d_in[5];
    const int*   edge2   = (const int*)d_in[6];
    const float* pseudo2 = (const float*)d_in[7];
    const float* skip2   = (const float*)d_in[8];
    const float* W1a = (const float*)d_in[9];
    const float* R1a = (const float*)d_in[10];
    const float* b1a = (const float*)d_in[11];
    const float* W2a = (const float*)d_in[12];
    const float* R2a = (const float*)d_in[13];
    const float* b2a = (const float*)d_in[14];
    const float* W1b = (const float*)d_in[15];
    const float* R1b = (const float*)d_in[16];
    const float* b1b = (const float*)d_in[17];
    const float* W2b = (const float*)d_in[18];
    const float* R2b = (const float*)d_in[19];
    const float* b2b = (const float*)d_in[20];

    float *basisP, *ZP, *bufA, *bufB;
    cudaGetSymbolAddress((void**)&basisP, g_basis);
    cudaGetSymbolAddress((void**)&ZP, g_Z);
    cudaGetSymbolAddress((void**)&bufA, g_bufA);
    cudaGetSymbolAddress((void**)&bufB, g_bufB);

    const int N1 = N1C, N2 = N2C, E1 = E1C, E2 = E2C;

    // ===================== Level 1: 64 -> 32 (N1, E1) =====================
    basis_kernel<<<(E1 + 255) / 256, 256>>>(pseudo1, basisP, E1);

    // conv1: x = x0[unpool1]
    node_kernel<64, 32><<<N1 / 32, 128>>>(x0, 64, nullptr, unpool1, 0,
                                          W1a, R1a, b1a, ZP, bufA, N1);
    edge_kernel<32><<<(E1 * 8 + 255) / 256, 256>>>(edge1, edge1 + E1, basisP, ZP, bufA, E1);

    // conv2: concat(relu(conv1), skip1), same weights W1a/R1a/b1a
    node_kernel<64, 32><<<N1 / 32, 128>>>(bufA, 32, skip1, nullptr, 1,
                                          W1a, R1a, b1a, ZP, bufB, N1);
    edge_kernel<32><<<(E1 * 8 + 255) / 256, 256>>>(edge1, edge1 + E1, basisP, ZP, bufB, E1);

    // conv3: relu(conv2) with W2a
    node_kernel<32, 32><<<N1 / 32, 128>>>(bufB, 32, nullptr, nullptr, 1,
                                          W2a, R2a, b2a, ZP, bufA, N1);
    edge_kernel<32><<<(E1 * 8 + 255) / 256, 256>>>(edge1, edge1 + E1, basisP, ZP, bufA, E1);
    // bufA = h1 (pre-relu; relu applied at gather below)

    // ===================== Level 2: 32 -> 16 (N2, E2) =====================
    basis_kernel<<<(E2 + 255) / 256, 256>>>(pseudo2, basisP, E2);

    // conv1: x = relu(h1)[unpool2]
    node_kernel<32, 16><<<N2 / 32, 128>>>(bufA, 32, nullptr, unpool2, 1,
                                          W1b, R1b, b1b, ZP, bufB, N2);
    edge_kernel<16><<<(E2 * 4 + 255) / 256, 256>>>(edge2, edge2 + E2, basisP, ZP, bufB, E2);

    // conv2: concat(relu(conv1), skip2), same weights W1b/R1b/b1b
    node_kernel<32, 16><<<N2 / 32, 128>>>(bufB, 16, skip2, nullptr, 1,
                                          W1b, R1b, b1b, ZP, bufA, N2);
    edge_kernel<16><<<(E2 * 4 + 255) / 256, 256>>>(edge2, edge2 + E2, basisP, ZP, bufA, E2);

    // conv3: relu(conv2) with W2b
    node_kernel<16, 16><<<N2 / 32, 128>>>(bufA, 16, nullptr, nullptr, 1,
                                          W2b, R2b, b2b, ZP, bufB, N2);
    edge_kernel<16><<<(E2 * 4 + 255) / 256, 256>>>(edge2, edge2 + E2, basisP, ZP, bufB, E2);

    // final relu -> output
    int nOut = N2 * 16;
    relu_copy_kernel<<<(nOut + 255) / 256, 256>>>(bufB, (float*)d_out, nOut);
}

// round 2
// speedup vs baseline: 1.4025x; 1.4025x over previous
#include <cuda_runtime.h>
#include <cstdint>

// Problem constants (fixed by the dataset)
#define N0C 10000
#define N1C 40000
#define N2C 160000
#define E1C 240000
#define E2C 960000

// Static scratch (no allocation allowed)
__device__ float g_Z[N2C * 9 * 16];                // 92.2 MB (>= N1C*9*32)
__device__ float g_bufA[N2C * 32];                 // 20.5 MB
__device__ float g_bufB[N2C * 32];                 // 20.5 MB
__device__ float g_Wp[40960];                      // packed weights (all 4 sets)

// packed-weight offsets
#define OFF_W1A 0              // 64*320 = 20480
#define OFF_W2A 20480          // 32*320 = 10240
#define OFF_W1B 30720          // 32*160 = 5120
#define OFF_W2B 35840          // 16*160 = 2560

// ---------------------------------------------------------------------------
// Pack W[9,CIN,COUT] + R[CIN,COUT] -> Wp[CIN][10*COUT]
// ---------------------------------------------------------------------------
__global__ void pack_kernel(const float* __restrict__ W,
                            const float* __restrict__ R,
                            float* __restrict__ Wp, int CIN, int COUT) {
    int i = blockIdx.x * blockDim.x + threadIdx.x;
    int OUTW = 10 * COUT;
    if (i >= CIN * OUTW) return;
    int c = i / OUTW;
    int j = i - c * OUTW;
    float v;
    if (j < 9 * COUT) {
        int k = j / COUT;
        int co = j - k * COUT;
        v = W[((size_t)k * CIN + c) * COUT + co];
    } else {
        v = R[(size_t)c * COUT + (j - 9 * COUT)];
    }
    Wp[i] = v;
}

// ---------------------------------------------------------------------------
// Node kernel: Z[n, 0:9*COUT] = X[n,:] @ Wcat ; O[n,:] = X[n,:] @ R + b
// X row n assembled on the fly: r = gidx? gidx[n] : n
//   c <  CA : xA[r*CA + c]  (ReLU'd if reluA)
//   c >= CA : xB[r*(CIN-CA) + (c-CA)]  (skip connection, raw)
// Block: 128 threads, 32 nodes x CT(=160) output cols (blockIdx.y tiles cols).
// Thread: 8 nodes x TN(=5) cols. acc = 40 regs.
// ---------------------------------------------------------------------------
template <int CIN, int COUT>
__global__ void __launch_bounds__(128, 4)
node_kernel(const float* __restrict__ xA, int CA,
            const float* __restrict__ xB,
            const int* __restrict__ gidx, int reluA,
            const float* __restrict__ Wp,
            const float* __restrict__ bias,
            float* __restrict__ Z, float* __restrict__ O) {
    constexpr int OUTW = 10 * COUT;
    constexpr int CT = 160;
    constexpr int TN = CT / 32;          // 5
    constexpr int NCH = CIN / 16;

    __shared__ float xs[16][32];
    __shared__ float ws[16][CT];
    __shared__ int rows[32];

    int tid = threadIdx.x;
    int lane = tid & 31;
    int ty = tid >> 5;
    int nodeBase = blockIdx.x * 32;
    int colBase = blockIdx.y * CT;

    if (tid < 32) {
        int n = nodeBase + tid;
        rows[tid] = gidx ? gidx[n] : n;
    }
    __syncthreads();

    float acc[8][TN];
#pragma unroll
    for (int m = 0; m < 8; m++)
#pragma unroll
        for (int t = 0; t < TN; t++) acc[m][t] = 0.f;

#pragma unroll
    for (int c0 = 0; c0 < NCH; c0++) {
        // ---- stage x tile: 32 nodes x 16 channels, one float4 per thread ----
        {
            int node = tid & 31;
            int sub = tid >> 5;              // 0..3 -> channels sub*4..sub*4+3
            int c = c0 * 16 + sub * 4;
            int r = rows[node];
            float4 v;
            if (c < CA) {
                v = *reinterpret_cast<const float4*>(xA + (size_t)r * CA + c);
                if (reluA) {
                    v.x = fmaxf(v.x, 0.f); v.y = fmaxf(v.y, 0.f);
                    v.z = fmaxf(v.z, 0.f); v.w = fmaxf(v.w, 0.f);
                }
            } else {
                v = *reinterpret_cast<const float4*>(
                        xB + (size_t)r * (CIN - CA) + (c - CA));
            }
            int cc = sub * 4;
            xs[cc + 0][node] = v.x;
            xs[cc + 1][node] = v.y;
            xs[cc + 2][node] = v.z;
            xs[cc + 3][node] = v.w;
        }
        // ---- stage weight tile: 16 rows x CT cols (contiguous, packed) ----
#pragma unroll
        for (int i = tid; i < 16 * (CT / 4); i += 128) {
            int rr = i / (CT / 4);
            int cc = i - rr * (CT / 4);
            float4 w = *reinterpret_cast<const float4*>(
                Wp + (size_t)(c0 * 16 + rr) * OUTW + colBase + cc * 4);
            *reinterpret_cast<float4*>(&ws[rr][cc * 4]) = w;
        }
        __syncthreads();
#pragma unroll
        for (int k = 0; k < 16; k++) {
            float4 xv0 = *reinterpret_cast<const float4*>(&xs[k][ty * 8]);
            float4 xv1 = *reinterpret_cast<const float4*>(&xs[k][ty * 8 + 4]);
            float xv[8] = {xv0.x, xv0.y, xv0.z, xv0.w, xv1.x, xv1.y, xv1.z, xv1.w};
            float wv[TN];
#pragma unroll
            for (int t = 0; t < TN; t++) wv[t] = ws[k][lane + 32 * t];
#pragma unroll
            for (int m = 0; m < 8; m++)
#pragma unroll
                for (int t = 0; t < TN; t++)
                    acc[m][t] = fmaf(xv[m], wv[t], acc[m][t]);
        }
        __syncthreads();
    }

#pragma unroll
    for (int m = 0; m < 8; m++) {
        int n = nodeBase + ty * 8 + m;
#pragma unroll
        for (int t = 0; t < TN; t++) {
            int j = colBase + lane + 32 * t;
            if (j < 9 * COUT) {
                Z[(size_t)n * (9 * COUT) + j] = acc[m][t];
            } else {
                int co = j - 9 * COUT;
                O[(size_t)n * COUT + co] = acc[m][t] + bias[co];
            }
        }
    }
}

// ---------------------------------------------------------------------------
// Edge kernel: m_e = sum_k basis(pseudo_e)[k] * Z[src_e, k, :], RED into O[dst].
// 8 channels per thread (2 float4 accumulators), basis computed inline,
// scatter via red.global.add.v4.f32 (2 vector reductions per thread).
// ---------------------------------------------------------------------------
template <int COUT>
__global__ void edge_kernel(const int* __restrict__ src,
                            const int* __restrict__ dst,
                            const float* __restrict__ pseudo,
                            const float* __restrict__ Z,
                            float* __restrict__ O, int E) {
    constexpr int TPE = COUT / 8;
    int tid = blockIdx.x * blockDim.x + threadIdx.x;
    int e = tid / TPE;
    int g = tid - e * TPE;     // channel group: channels [g*8, g*8+8)
    if (e >= E) return;

    float t0 = __ldg(pseudo + 2 * e + 0);
    float t1 = __ldg(pseudo + 2 * e + 1);
    float a0 = 0.5f * (1.f - t0) * (1.f - t0);
    float a1 = -t0 * t0 + t0 + 0.5f;
    float a2 = 0.5f * t0 * t0;
    float c0 = 0.5f * (1.f - t1) * (1.f - t1);
    float c1 = -t1 * t1 + t1 + 0.5f;
    float c2 = 0.5f * t1 * t1;
    float b[9] = {a0 * c0, a0 * c1, a0 * c2,
                  a1 * c0, a1 * c1, a1 * c2,
                  a2 * c0, a2 * c1, a2 * c2};

    int s = __ldg(src + e);
    int d = __ldg(dst + e);
    const float4* zr =
        reinterpret_cast<const float4*>(Z + (size_t)s * (9 * COUT)) + g * 2;
    float4 acc0 = make_float4(0.f, 0.f, 0.f, 0.f);
    float4 acc1 = make_float4(0.f, 0.f, 0.f, 0.f);
#pragma unroll
    for (int k = 0; k < 9; k++) {
        float bk = b[k];
        float4 z0 = __ldg(zr + k * (COUT / 4) + 0);
        float4 z1 = __ldg(zr + k * (COUT / 4) + 1);
        acc0.x = fmaf(bk, z0.x, acc0.x);
        acc0.y = fmaf(bk, z0.y, acc0.y);
        acc0.z = fmaf(bk, z0.z, acc0.z);
        acc0.w = fmaf(bk, z0.w, acc0.w);
        acc1.x = fmaf(bk, z1.x, acc1.x);
        acc1.y = fmaf(bk, z1.y, acc1.y);
        acc1.z = fmaf(bk, z1.z, acc1.z);
        acc1.w = fmaf(bk, z1.w, acc1.w);
    }
    float* o = O + (size_t)d * COUT + g * 8;
    asm volatile("red.global.add.v4.f32 [%0], {%1, %2, %3, %4};"
                 :: "l"(o), "f"(acc0.x), "f"(acc0.y), "f"(acc0.z), "f"(acc0.w)
                 : "memory");
    asm volatile("red.global.add.v4.f32 [%0], {%1, %2, %3, %4};"
                 :: "l"(o + 4), "f"(acc1.x), "f"(acc1.y), "f"(acc1.z), "f"(acc1.w)
                 : "memory");
}

__global__ void relu_copy4_kernel(const float4* __restrict__ in,
                                  float4* __restrict__ out, int n4) {
    int i = blockIdx.x * blockDim.x + threadIdx.x;
    if (i >= n4) return;
    float4 v = in[i];
    v.x = fmaxf(v.x, 0.f); v.y = fmaxf(v.y, 0.f);
    v.z = fmaxf(v.z, 0.f); v.w = fmaxf(v.w, 0.f);
    out[i] = v;
}

// ---------------------------------------------------------------------------
extern "C" void kernel_launch(void* const* d_in, const int* in_sizes, int n_in,
                              void* d_out, int out_size) {
    const float* x0      = (const float*)d_in[0];
    const int*   unpool1 = (const int*)d_in[1];
    const int*   edge1   = (const int*)d_in[2];
    const float* pseudo1 = (const float*)d_in[3];
    const float* skip1   = (const float*)d_in[4];
    const int*   unpool2 = (const int*)d_in[5];
    const int*   edge2   = (const int*)d_in[6];
    const float* pseudo2 = (const float*)d_in[7];
    const float* skip2   = (const float*)d_in[8];
    const float* W1a = (const float*)d_in[9];
    const float* R1a = (const float*)d_in[10];
    const float* b1a = (const float*)d_in[11];
    const float* W2a = (const float*)d_in[12];
    const float* R2a = (const float*)d_in[13];
    const float* b2a = (const float*)d_in[14];
    const float* W1b = (const float*)d_in[15];
    const float* R1b = (const float*)d_in[16];
    const float* b1b = (const float*)d_in[17];
    const float* W2b = (const float*)d_in[18];
    const float* R2b = (const float*)d_in[19];
    const float* b2b = (const float*)d_in[20];

    float *ZP, *bufA, *bufB, *Wp;
    cudaGetSymbolAddress((void**)&ZP, g_Z);
    cudaGetSymbolAddress((void**)&bufA, g_bufA);
    cudaGetSymbolAddress((void**)&bufB, g_bufB);
    cudaGetSymbolAddress((void**)&Wp, g_Wp);

    const int N1 = N1C, N2 = N2C, E1 = E1C, E2 = E2C;

    // ---- pack weights (independent, cheap) ----
    pack_kernel<<<(64 * 320 + 255) / 256, 256>>>(W1a, R1a, Wp + OFF_W1A, 64, 32);
    pack_kernel<<<(32 * 320 + 255) / 256, 256>>>(W2a, R2a, Wp + OFF_W2A, 32, 32);
    pack_kernel<<<(32 * 160 + 255) / 256, 256>>>(W1b, R1b, Wp + OFF_W1B, 32, 16);
    pack_kernel<<<(16 * 160 + 255) / 256, 256>>>(W2b, R2b, Wp + OFF_W2B, 16, 16);

    // ===================== Level 1: 64 -> 32 (N1, E1) =====================
    // conv1: x = x0[unpool1]
    node_kernel<64, 32><<<dim3(N1 / 32, 2), 128>>>(x0, 64, nullptr, unpool1, 0,
                                                   Wp + OFF_W1A, b1a, ZP, bufA);
    edge_kernel<32><<<(E1 * 4 + 255) / 256, 256>>>(edge1, edge1 + E1, pseudo1, ZP, bufA, E1);

    // conv2: concat(relu(conv1), skip1), same weights W1a/R1a/b1a
    node_kernel<64, 32><<<dim3(N1 / 32, 2), 128>>>(bufA, 32, skip1, nullptr, 1,
                                                   Wp + OFF_W1A, b1a, ZP, bufB);
    edge_kernel<32><<<(E1 * 4 + 255) / 256, 256>>>(edge1, edge1 + E1, pseudo1, ZP, bufB, E1);

    // conv3: relu(conv2) with W2a
    node_kernel<32, 32><<<dim3(N1 / 32, 2), 128>>>(bufB, 32, nullptr, nullptr, 1,
                                                   Wp + OFF_W2A, b2a, ZP, bufA);
    edge_kernel<32><<<(E1 * 4 + 255) / 256, 256>>>(edge1, edge1 + E1, pseudo1, ZP, bufA, E1);
    // bufA = h1 (pre-relu; relu applied at gather below)

    // ===================== Level 2: 32 -> 16 (N2, E2) =====================
    // conv1: x = relu(h1)[unpool2]
    node_kernel<32, 16><<<dim3(N2 / 32, 1), 128>>>(bufA, 32, nullptr, unpool2, 1,
                                                   Wp + OFF_W1B, b1b, ZP, bufB);
    edge_kernel<16><<<(E2 * 2 + 255) / 256, 256>>>(edge2, edge2 + E2, pseudo2, ZP, bufB, E2);

    // conv2: concat(relu(conv1), skip2), same weights W1b/R1b/b1b
    node_kernel<32, 16><<<dim3(N2 / 32, 1), 128>>>(bufB, 16, skip2, nullptr, 1,
                                                   Wp + OFF_W1B, b1b, ZP, bufA);
    edge_kernel<16><<<(E2 * 2 + 255) / 256, 256>>>(edge2, edge2 + E2, pseudo2, ZP, bufA, E2);

    // conv3: relu(conv2) with W2b
    node_kernel<16, 16><<<dim3(N2 / 32, 1), 128>>>(bufA, 16, nullptr, nullptr, 1,
                                                   Wp + OFF_W2B, b2b, ZP, bufB);
    edge_kernel<16><<<(E2 * 2 + 255) / 256, 256>>>(edge2, edge2 + E2, pseudo2, ZP, bufB, E2);

    // final relu -> output
    int n4 = N2 * 16 / 4;
    relu_copy4_kernel<<<(n4 + 255) / 256, 256>>>((const float4*)bufB,
                                                 (float4*)d_out, n4);
}

// round 3
// speedup vs baseline: 1.8223x; 1.2993x over previous
#include <cuda_runtime.h>
#include <cuda_fp16.h>
#include <cstdint>

// Problem constants (fixed by the dataset)
#define N0C 10000
#define N1C 40000
#define N2C 160000
#define E1C 240000
#define E2C 960000

// Static scratch (no allocation allowed)
__device__ __half g_Z[N2C * 9 * 16];               // 46.1 MB (>= N1C*9*32 halves)
__device__ float g_bufA[N2C * 32];                 // 20.5 MB
__device__ float g_bufB[N2C * 32];                 // 20.5 MB
__device__ float g_Wp[40960];                      // packed weights (all 4 sets)

// packed-weight offsets
#define OFF_W1A 0              // 64*320 = 20480
#define OFF_W2A 20480          // 32*320 = 10240
#define OFF_W1B 30720          // 32*160 = 5120
#define OFF_W2B 35840          // 16*160 = 2560

// ---------------------------------------------------------------------------
// Pack all 4 weight sets: W[9,CIN,COUT] + R[CIN,COUT] -> Wp[CIN][10*COUT]
// ---------------------------------------------------------------------------
__device__ __forceinline__ void pack_one(const float* __restrict__ W,
                                         const float* __restrict__ R,
                                         float* __restrict__ Wp,
                                         int CIN, int COUT, int i) {
    int OUTW = 10 * COUT;
    int c = i / OUTW;
    int j = i - c * OUTW;
    float v;
    if (j < 9 * COUT) {
        int k = j / COUT;
        int co = j - k * COUT;
        v = W[((size_t)k * CIN + c) * COUT + co];
    } else {
        v = R[(size_t)c * COUT + (j - 9 * COUT)];
    }
    Wp[i] = v;
}

__global__ void pack_all_kernel(const float* W1a, const float* R1a,
                                const float* W2a, const float* R2a,
                                const float* W1b, const float* R1b,
                                const float* W2b, const float* R2b,
                                float* __restrict__ Wp) {
    int i = blockIdx.x * blockDim.x + threadIdx.x;
    if (i < 20480) {
        pack_one(W1a, R1a, Wp + OFF_W1A, 64, 32, i);
    } else if (i < 30720) {
        pack_one(W2a, R2a, Wp + OFF_W2A, 32, 32, i - 20480);
    } else if (i < 35840) {
        pack_one(W1b, R1b, Wp + OFF_W1B, 32, 16, i - 30720);
    } else if (i < 38400) {
        pack_one(W2b, R2b, Wp + OFF_W2B, 16, 16, i - 35840);
    }
}

// ---------------------------------------------------------------------------
// Node kernel: Z[n, 0:9*COUT] = X[n,:] @ Wcat (fp16) ; O[n,:] = X[n,:] @ R + b
// X row n assembled on the fly: r = gidx? gidx[n] : n
//   c <  CA : xA[r*CA + c]  (ReLU'd if reluA)
//   c >= CA : xB[r*(CIN-CA) + (c-CA)]  (skip connection, raw)
// Block: 128 threads, 32 nodes x CT(=160) output cols (blockIdx.y tiles cols).
// ---------------------------------------------------------------------------
template <int CIN, int COUT>
__global__ void __launch_bounds__(128, 4)
node_kernel(const float* __restrict__ xA, int CA,
            const float* __restrict__ xB,
            const int* __restrict__ gidx, int reluA,
            const float* __restrict__ Wp,
            const float* __restrict__ bias,
            __half* __restrict__ Z, float* __restrict__ O) {
    constexpr int OUTW = 10 * COUT;
    constexpr int CT = 160;
    constexpr int TN = CT / 32;          // 5
    constexpr int NCH = CIN / 16;

    __shared__ float xs[16][32];
    __shared__ float ws[16][CT];
    __shared__ int rows[32];

    int tid = threadIdx.x;
    int lane = tid & 31;
    int ty = tid >> 5;
    int nodeBase = blockIdx.x * 32;
    int colBase = blockIdx.y * CT;

    if (tid < 32) {
        int n = nodeBase + tid;
        rows[tid] = gidx ? gidx[n] : n;
    }
    __syncthreads();

    float acc[8][TN];
#pragma unroll
    for (int m = 0; m < 8; m++)
#pragma unroll
        for (int t = 0; t < TN; t++) acc[m][t] = 0.f;

#pragma unroll
    for (int c0 = 0; c0 < NCH; c0++) {
        // ---- stage x tile: 32 nodes x 16 channels, one float4 per thread ----
        {
            int node = tid & 31;
            int sub = tid >> 5;              // 0..3 -> channels sub*4..sub*4+3
            int c = c0 * 16 + sub * 4;
            int r = rows[node];
            float4 v;
            if (c < CA) {
                v = *reinterpret_cast<const float4*>(xA + (size_t)r * CA + c);
                if (reluA) {
                    v.x = fmaxf(v.x, 0.f); v.y = fmaxf(v.y, 0.f);
                    v.z = fmaxf(v.z, 0.f); v.w = fmaxf(v.w, 0.f);
                }
            } else {
                v = *reinterpret_cast<const float4*>(
                        xB + (size_t)r * (CIN - CA) + (c - CA));
            }
            int cc = sub * 4;
            xs[cc + 0][node] = v.x;
            xs[cc + 1][node] = v.y;
            xs[cc + 2][node] = v.z;
            xs[cc + 3][node] = v.w;
        }
        // ---- stage weight tile: 16 rows x CT cols (contiguous, packed) ----
#pragma unroll
        for (int i = tid; i < 16 * (CT / 4); i += 128) {
            int rr = i / (CT / 4);
            int cc = i - rr * (CT / 4);
            float4 w = *reinterpret_cast<const float4*>(
                Wp + (size_t)(c0 * 16 + rr) * OUTW + colBase + cc * 4);
            *reinterpret_cast<float4*>(&ws[rr][cc * 4]) = w;
        }
        __syncthreads();
#pragma unroll
        for (int k = 0; k < 16; k++) {
            float4 xv0 = *reinterpret_cast<const float4*>(&xs[k][ty * 8]);
            float4 xv1 = *reinterpret_cast<const float4*>(&xs[k][ty * 8 + 4]);
            float xv[8] = {xv0.x, xv0.y, xv0.z, xv0.w, xv1.x, xv1.y, xv1.z, xv1.w};
            float wv[TN];
#pragma unroll
            for (int t = 0; t < TN; t++) wv[t] = ws[k][lane + 32 * t];
#pragma unroll
            for (int m = 0; m < 8; m++)
#pragma unroll
                for (int t = 0; t < TN; t++)
                    acc[m][t] = fmaf(xv[m], wv[t], acc[m][t]);
        }
        __syncthreads();
    }

#pragma unroll
    for (int m = 0; m < 8; m++) {
        int n = nodeBase + ty * 8 + m;
#pragma unroll
        for (int t = 0; t < TN; t++) {
            int j = colBase + lane + 32 * t;
            if (j < 9 * COUT) {
                Z[(size_t)n * (9 * COUT) + j] = __float2half_rn(acc[m][t]);
            } else {
                int co = j - 9 * COUT;
                O[(size_t)n * COUT + co] = acc[m][t] + bias[co];
            }
        }
    }
}

// ---------------------------------------------------------------------------
// Edge kernel: m_e = sum_k basis(pseudo_e)[k] * Z[src_e, k, :], RED into O[dst].
// 8 channels per thread; Z is fp16 -> one 16B vector load per k per thread.
// Scatter via red.global.add.v4.f32 (2 vector reductions per thread).
// ---------------------------------------------------------------------------
template <int COUT>
__global__ void edge_kernel(const int* __restrict__ src,
                            const int* __restrict__ dst,
                            const float* __restrict__ pseudo,
                            const __half* __restrict__ Z,
                            float* __restrict__ O, int E) {
    constexpr int TPE = COUT / 8;
    int tid = blockIdx.x * blockDim.x + threadIdx.x;
    int e = tid / TPE;
    int g = tid - e * TPE;     // channel group: channels [g*8, g*8+8)
    if (e >= E) return;

    float t0 = __ldg(pseudo + 2 * e + 0);
    float t1 = __ldg(pseudo + 2 * e + 1);
    float a0 = 0.5f * (1.f - t0) * (1.f - t0);
    float a1 = -t0 * t0 + t0 + 0.5f;
    float a2 = 0.5f * t0 * t0;
    float c0 = 0.5f * (1.f - t1) * (1.f - t1);
    float c1 = -t1 * t1 + t1 + 0.5f;
    float c2 = 0.5f * t1 * t1;
    float b[9] = {a0 * c0, a0 * c1, a0 * c2,
                  a1 * c0, a1 * c1, a1 * c2,
                  a2 * c0, a2 * c1, a2 * c2};

    int s = __ldg(src + e);
    int d = __ldg(dst + e);
    const __half* zb = Z + (size_t)s * (9 * COUT) + g * 8;
    float4 acc0 = make_float4(0.f, 0.f, 0.f, 0.f);
    float4 acc1 = make_float4(0.f, 0.f, 0.f, 0.f);
#pragma unroll
    for (int k = 0; k < 9; k++) {
        float bk = b[k];
        uint4 raw = *reinterpret_cast<const uint4*>(zb + k * COUT);
        float2 f0 = __half22float2(*reinterpret_cast<const __half2*>(&raw.x));
        float2 f1 = __half22float2(*reinterpret_cast<const __half2*>(&raw.y));
        float2 f2 = __half22float2(*reinterpret_cast<const __half2*>(&raw.z));
        float2 f3 = __half22float2(*reinterpret_cast<const __half2*>(&raw.w));
        acc0.x = fmaf(bk, f0.x, acc0.x);
        acc0.y = fmaf(bk, f0.y, acc0.y);
        acc0.z = fmaf(bk, f1.x, acc0.z);
        acc0.w = fmaf(bk, f1.y, acc0.w);
        acc1.x = fmaf(bk, f2.x, acc1.x);
        acc1.y = fmaf(bk, f2.y, acc1.y);
        acc1.z = fmaf(bk, f3.x, acc1.z);
        acc1.w = fmaf(bk, f3.y, acc1.w);
    }
    float* o = O + (size_t)d * COUT + g * 8;
    asm volatile("red.global.add.v4.f32 [%0], {%1, %2, %3, %4};"
                 :: "l"(o), "f"(acc0.x), "f"(acc0.y), "f"(acc0.z), "f"(acc0.w)
                 : "memory");
    asm volatile("red.global.add.v4.f32 [%0], {%1, %2, %3, %4};"
                 :: "l"(o + 4), "f"(acc1.x), "f"(acc1.y), "f"(acc1.z), "f"(acc1.w)
                 : "memory");
}

__global__ void relu_copy4_kernel(const float4* __restrict__ in,
                                  float4* __restrict__ out, int n4) {
    int i = blockIdx.x * blockDim.x + threadIdx.x;
    if (i >= n4) return;
    float4 v = in[i];
    v.x = fmaxf(v.x, 0.f); v.y = fmaxf(v.y, 0.f);
    v.z = fmaxf(v.z, 0.f); v.w = fmaxf(v.w, 0.f);
    out[i] = v;
}

// ---------------------------------------------------------------------------
extern "C" void kernel_launch(void* const* d_in, const int* in_sizes, int n_in,
                              void* d_out, int out_size) {
    const float* x0      = (const float*)d_in[0];
    const int*   unpool1 = (const int*)d_in[1];
    const int*   edge1   = (const int*)d_in[2];
    const float* pseudo1 = (const float*)d_in[3];
    const float* skip1   = (const float*)d_in[4];
    const int*   unpool2 = (const int*)d_in[5];
    const int*   edge2   = (const int*)d_in[6];
    const float* pseudo2 = (const float*)d_in[7];
    const float* skip2   = (const float*)d_in[8];
    const float* W1a = (const float*)d_in[9];
    const float* R1a = (const float*)d_in[10];
    const float* b1a = (const float*)d_in[11];
    const float* W2a = (const float*)d_in[12];
    const float* R2a = (const float*)d_in[13];
    const float* b2a = (const float*)d_in[14];
    const float* W1b = (const float*)d_in[15];
    const float* R1b = (const float*)d_in[16];
    const float* b1b = (const float*)d_in[17];
    const float* W2b = (const float*)d_in[18];
    const float* R2b = (const float*)d_in[19];
    const float* b2b = (const float*)d_in[20];

    __half* ZP;
    float *bufA, *bufB, *Wp;
    cudaGetSymbolAddress((void**)&ZP, g_Z);
    cudaGetSymbolAddress((void**)&bufA, g_bufA);
    cudaGetSymbolAddress((void**)&bufB, g_bufB);
    cudaGetSymbolAddress((void**)&Wp, g_Wp);

    const int N1 = N1C, N2 = N2C, E1 = E1C, E2 = E2C;

    // ---- pack all weights in one launch ----
    pack_all_kernel<<<(38400 + 255) / 256, 256>>>(W1a, R1a, W2a, R2a,
                                                  W1b, R1b, W2b, R2b, Wp);

    // ===================== Level 1: 64 -> 32 (N1, E1) =====================
    // conv1: x = x0[unpool1]
    node_kernel<64, 32><<<dim3(N1 / 32, 2), 128>>>(x0, 64, nullptr, unpool1, 0,
                                                   Wp + OFF_W1A, b1a, ZP, bufA);
    edge_kernel<32><<<(E1 * 4 + 255) / 256, 256>>>(edge1, edge1 + E1, pseudo1, ZP, bufA, E1);

    // conv2: concat(relu(conv1), skip1), same weights W1a/R1a/b1a
    node_kernel<64, 32><<<dim3(N1 / 32, 2), 128>>>(bufA, 32, skip1, nullptr, 1,
                                                   Wp + OFF_W1A, b1a, ZP, bufB);
    edge_kernel<32><<<(E1 * 4 + 255) / 256, 256>>>(edge1, edge1 + E1, pseudo1, ZP, bufB, E1);

    // conv3: relu(conv2) with W2a
    node_kernel<32, 32><<<dim3(N1 / 32, 2), 128>>>(bufB, 32, nullptr, nullptr, 1,
                                                   Wp + OFF_W2A, b2a, ZP, bufA);
    edge_kernel<32><<<(E1 * 4 + 255) / 256, 256>>>(edge1, edge1 + E1, pseudo1, ZP, bufA, E1);
    // bufA = h1 (pre-relu; relu applied at gather below)

    // ===================== Level 2: 32 -> 16 (N2, E2) =====================
    // conv1: x = relu(h1)[unpool2]
    node_kernel<32, 16><<<dim3(N2 / 32, 1), 128>>>(bufA, 32, nullptr, unpool2, 1,
                                                   Wp + OFF_W1B, b1b, ZP, bufB);
    edge_kernel<16><<<(E2 * 2 + 255) / 256, 256>>>(edge2, edge2 + E2, pseudo2, ZP, bufB, E2);

    // conv2: concat(relu(conv1), skip2), same weights W1b/R1b/b1b
    node_kernel<32, 16><<<dim3(N2 / 32, 1), 128>>>(bufB, 16, skip2, nullptr, 1,
                                                   Wp + OFF_W1B, b1b, ZP, bufA);
    edge_kernel<16><<<(E2 * 2 + 255) / 256, 256>>>(edge2, edge2 + E2, pseudo2, ZP, bufA, E2);

    // conv3: relu(conv2) with W2b
    node_kernel<16, 16><<<dim3(N2 / 32, 1), 128>>>(bufA, 16, nullptr, nullptr, 1,
                                                   Wp + OFF_W2B, b2b, ZP, bufB);
    edge_kernel<16><<<(E2 * 2 + 255) / 256, 256>>>(edge2, edge2 + E2, pseudo2, ZP, bufB, E2);

    // final relu -> output
    int n4 = N2 * 16 / 4;
    relu_copy4_kernel<<<(n4 + 255) / 256, 256>>>((const float4*)bufB,
                                                 (float4*)d_out, n4);
}